// round 1
// baseline (speedup 1.0000x reference)
#include <cuda_runtime.h>

// Problem constants
#define BATCH 16
#define LQ    2048
#define LK    2048
#define DDIM  1024

typedef unsigned long long ull;

// ---- packed f32x2 helpers (FFMA2 path; ptxas never emits this from C++) ----
static __device__ __forceinline__ ull pk2(float lo, float hi) {
    ull r;
    asm("mov.b64 %0, {%1, %2};" : "=l"(r) : "f"(lo), "f"(hi));
    return r;
}
static __device__ __forceinline__ ull fma2(ull a, ull b, ull c) {
    ull d;
    asm("fma.rn.f32x2 %0, %1, %2, %3;" : "=l"(d) : "l"(a), "l"(b), "l"(c));
    return d;
}
static __device__ __forceinline__ float2 up2(ull v) {
    float2 r;
    asm("mov.b64 {%0, %1}, %2;" : "=f"(r.x), "=f"(r.y) : "l"(v));
    return r;
}

// ----------------------------------------------------------------------------
// Tiled batched GEMM: C[M,N] = A[M,K] * op(B)
//   BT = true : B is [N,K] row-major (K-contiguous)  -> C = A * B^T   (Q·V^T)
//   BT = false: B is [K,N] row-major (N-contiguous)  -> C = A * B     (attn·V)
// CTA tile 128x128, 256 threads, 8x8 microtile per thread, KTILE=8,
// double-buffered shared memory, packed f32x2 FMAs in the inner loop.
// All dims are exact multiples of the tiles for this problem (no bounds checks).
// ----------------------------------------------------------------------------
template <bool BT>
__global__ __launch_bounds__(256, 2)
void gemm128(const float* __restrict__ Ag, const float* __restrict__ Bg,
             float* __restrict__ Cg,
             int K, int lda, int ldb, int ldc,
             long strideA, long strideB, long strideC)
{
    __shared__ __align__(16) float As[2][8][128];
    __shared__ __align__(16) float Bs[2][8][128];

    const int bcol = blockIdx.x * 128;
    const int brow = blockIdx.y * 128;
    const int bz   = blockIdx.z;

    const float* A  = Ag + (long)bz * strideA + (long)brow * lda;
    const float* Bp = Bg + (long)bz * strideB;
    float*       C  = Cg + (long)bz * strideC;

    const int tid = threadIdx.x;
    const int tx  = tid & 15;   // column group (8 cols each)
    const int ty  = tid >> 4;   // row group (8 rows each)

    // A tile loader: 128 rows x 8 k; each thread one float4 along k
    const int a_r = tid >> 1;          // 0..127
    const int a_k = (tid & 1) * 4;     // 0 or 4

    // B tile loader
    const int b_r = BT ? (tid >> 1) : (tid >> 5);          // BT: col idx / !BT: k row
    const int b_c = BT ? ((tid & 1) * 4) : ((tid & 31) * 4);

    ull acc[8][4];
#pragma unroll
    for (int i = 0; i < 8; ++i)
#pragma unroll
        for (int j = 0; j < 4; ++j) acc[i][j] = 0ull;

    const int NT = K >> 3;

    // prologue: tile 0 -> smem buffer 0
    float4 pa = *(const float4*)(A + (long)a_r * lda + a_k);
    float4 pb;
    if (BT) pb = *(const float4*)(Bp + (long)(bcol + b_r) * ldb + b_c);
    else    pb = *(const float4*)(Bp + (long)b_r * ldb + bcol + b_c);

    As[0][a_k + 0][a_r] = pa.x; As[0][a_k + 1][a_r] = pa.y;
    As[0][a_k + 2][a_r] = pa.z; As[0][a_k + 3][a_r] = pa.w;
    if (BT) {
        Bs[0][b_c + 0][b_r] = pb.x; Bs[0][b_c + 1][b_r] = pb.y;
        Bs[0][b_c + 2][b_r] = pb.z; Bs[0][b_c + 3][b_r] = pb.w;
    } else {
        *(float4*)&Bs[0][b_r][b_c] = pb;
    }
    __syncthreads();

    int buf = 0;
    for (int t = 0; t < NT; ++t) {
        // prefetch next tile into registers
        if (t + 1 < NT) {
            const int k0 = (t + 1) << 3;
            pa = *(const float4*)(A + (long)a_r * lda + k0 + a_k);
            if (BT) pb = *(const float4*)(Bp + (long)(bcol + b_r) * ldb + k0 + b_c);
            else    pb = *(const float4*)(Bp + (long)(k0 + b_r) * ldb + bcol + b_c);
        }

#pragma unroll
        for (int kk = 0; kk < 8; ++kk) {
            const float4 a0 = *(const float4*)&As[buf][kk][ty * 8];
            const float4 a1 = *(const float4*)&As[buf][kk][ty * 8 + 4];
            const ulonglong2 b01 = *(const ulonglong2*)&Bs[buf][kk][tx * 8];
            const ulonglong2 b23 = *(const ulonglong2*)&Bs[buf][kk][tx * 8 + 4];
            const ull bb0 = b01.x, bb1 = b01.y, bb2 = b23.x, bb3 = b23.y;
            const float av[8] = {a0.x, a0.y, a0.z, a0.w, a1.x, a1.y, a1.z, a1.w};
#pragma unroll
            for (int i = 0; i < 8; ++i) {
                const ull ad = pk2(av[i], av[i]);
                acc[i][0] = fma2(ad, bb0, acc[i][0]);
                acc[i][1] = fma2(ad, bb1, acc[i][1]);
                acc[i][2] = fma2(ad, bb2, acc[i][2]);
                acc[i][3] = fma2(ad, bb3, acc[i][3]);
            }
        }

        if (t + 1 < NT) {
            const int nb = buf ^ 1;
            As[nb][a_k + 0][a_r] = pa.x; As[nb][a_k + 1][a_r] = pa.y;
            As[nb][a_k + 2][a_r] = pa.z; As[nb][a_k + 3][a_r] = pa.w;
            if (BT) {
                Bs[nb][b_c + 0][b_r] = pb.x; Bs[nb][b_c + 1][b_r] = pb.y;
                Bs[nb][b_c + 2][b_r] = pb.z; Bs[nb][b_c + 3][b_r] = pb.w;
            } else {
                *(float4*)&Bs[nb][b_r][b_c] = pb;
            }
            __syncthreads();
            buf = nb;
        }
    }

    // epilogue: unpack and store 8x8 block as 2x float4 per row
#pragma unroll
    for (int i = 0; i < 8; ++i) {
        float o[8];
#pragma unroll
        for (int j = 0; j < 4; ++j) {
            const float2 v = up2(acc[i][j]);
            o[2 * j] = v.x; o[2 * j + 1] = v.y;
        }
        float* cp = C + (long)(brow + ty * 8 + i) * ldc + bcol + tx * 8;
        *(float4*)cp       = make_float4(o[0], o[1], o[2], o[3]);
        *(float4*)(cp + 4) = make_float4(o[4], o[5], o[6], o[7]);
    }
}

// ----------------------------------------------------------------------------
// Row softmax, in place. One block (256 threads) per row of 2048; each thread
// owns 8 contiguous elements. Max-subtracted, fp32 accumulation.
// ----------------------------------------------------------------------------
__global__ __launch_bounds__(256)
void softmax_rows(float* __restrict__ S)
{
    __shared__ float redmax[8];
    __shared__ float redsum[8];

    float* p = S + (size_t)blockIdx.x * LK;
    const int tid  = threadIdx.x;
    const int lane = tid & 31;
    const int warp = tid >> 5;

    float4 v0 = *(const float4*)(p + tid * 8);
    float4 v1 = *(const float4*)(p + tid * 8 + 4);

    float m = fmaxf(fmaxf(fmaxf(v0.x, v0.y), fmaxf(v0.z, v0.w)),
                    fmaxf(fmaxf(v1.x, v1.y), fmaxf(v1.z, v1.w)));
#pragma unroll
    for (int o = 16; o > 0; o >>= 1)
        m = fmaxf(m, __shfl_xor_sync(0xffffffffu, m, o));
    if (lane == 0) redmax[warp] = m;
    __syncthreads();

    float bm = redmax[0];
#pragma unroll
    for (int w = 1; w < 8; ++w) bm = fmaxf(bm, redmax[w]);

    float e0 = __expf(v0.x - bm), e1 = __expf(v0.y - bm);
    float e2 = __expf(v0.z - bm), e3 = __expf(v0.w - bm);
    float e4 = __expf(v1.x - bm), e5 = __expf(v1.y - bm);
    float e6 = __expf(v1.z - bm), e7 = __expf(v1.w - bm);

    float s = ((e0 + e1) + (e2 + e3)) + ((e4 + e5) + (e6 + e7));
#pragma unroll
    for (int o = 16; o > 0; o >>= 1)
        s += __shfl_xor_sync(0xffffffffu, s, o);
    if (lane == 0) redsum[warp] = s;
    __syncthreads();

    float total = redsum[0];
#pragma unroll
    for (int w = 1; w < 8; ++w) total += redsum[w];
    const float inv = 1.0f / total;

    *(float4*)(p + tid * 8)     = make_float4(e0 * inv, e1 * inv, e2 * inv, e3 * inv);
    *(float4*)(p + tid * 8 + 4) = make_float4(e4 * inv, e5 * inv, e6 * inv, e7 * inv);
}

// ----------------------------------------------------------------------------
// kernel_launch: S = Q·V^T -> softmax rows -> context = A·V
// Output layout: [context (B,LQ,D)][attn (B,LQ,LK)] in fp32.
// ----------------------------------------------------------------------------
extern "C" void kernel_launch(void* const* d_in, const int* in_sizes, int n_in,
                              void* d_out, int out_size)
{
    const float* Q = (const float*)d_in[0];
    const float* V = (const float*)d_in[1];
    float* ctx  = (float*)d_out;
    float* attn = (float*)d_out + (size_t)BATCH * LQ * DDIM;

    // GEMM1: attn_raw = Q @ V^T   (M=LQ, N=LK, K=D)
    gemm128<true><<<dim3(LK / 128, LQ / 128, BATCH), 256>>>(
        Q, V, attn, DDIM, DDIM, DDIM, LK,
        (long)LQ * DDIM, (long)LK * DDIM, (long)LQ * LK);

    // softmax over key axis, in place
    softmax_rows<<<BATCH * LQ, 256>>>(attn);

    // GEMM2: ctx = attn @ V       (M=LQ, N=D, K=LK)
    gemm128<false><<<dim3(DDIM / 128, LQ / 128, BATCH), 256>>>(
        attn, V, ctx, LK, LK, DDIM, DDIM,
        (long)LQ * LK, (long)LK * DDIM, (long)LQ * DDIM);
}

// round 3
// speedup vs baseline: 2.6212x; 2.6212x over previous
#include <cuda_runtime.h>
#include <cuda_bf16.h>
#include <cstdint>

#define BATCH 16
#define LQ    2048
#define LK    2048
#define DDIM  1024

// ---------------------------------------------------------------------------
// Scratch (device globals — sanctioned no-alloc scratch)
// ---------------------------------------------------------------------------
__device__ __nv_bfloat16 g_Qh[(size_t)BATCH * LQ * DDIM];
__device__ __nv_bfloat16 g_Ql[(size_t)BATCH * LQ * DDIM];
__device__ __nv_bfloat16 g_Vh[(size_t)BATCH * LK * DDIM];
__device__ __nv_bfloat16 g_Vl[(size_t)BATCH * LK * DDIM];
__device__ __nv_bfloat16 g_VTh[(size_t)BATCH * DDIM * LK];
__device__ __nv_bfloat16 g_VTl[(size_t)BATCH * DDIM * LK];
__device__ __nv_bfloat16 g_Ph[(size_t)BATCH * LQ * LK];
__device__ __nv_bfloat16 g_Pl[(size_t)BATCH * LQ * LK];

// ---------------------------------------------------------------------------
// PTX helpers (plain sm_80+ PTX only — no arch-suffix-gated instructions)
// ---------------------------------------------------------------------------
static __device__ __forceinline__ uint32_t smem_u32(const void* p) {
    uint32_t a;
    asm("{ .reg .u64 t; cvta.to.shared.u64 t, %1; cvt.u32.u64 %0, t; }"
        : "=r"(a) : "l"(p));
    return a;
}
static __device__ __forceinline__ void cpa16(uint32_t dst, const void* src) {
    asm volatile("cp.async.cg.shared.global [%0], [%1], 16;"
                 :: "r"(dst), "l"(src) : "memory");
}
static __device__ __forceinline__ void cp_commit() {
    asm volatile("cp.async.commit_group;" ::: "memory");
}
template <int N> static __device__ __forceinline__ void cp_wait() {
    asm volatile("cp.async.wait_group %0;" :: "n"(N) : "memory");
}
static __device__ __forceinline__ void ldm4(uint32_t* r, uint32_t addr) {
    asm volatile("ldmatrix.sync.aligned.m8n8.x4.shared.b16 {%0,%1,%2,%3}, [%4];"
                 : "=r"(r[0]), "=r"(r[1]), "=r"(r[2]), "=r"(r[3]) : "r"(addr));
}
static __device__ __forceinline__ void mma16816(float* c, const uint32_t* a,
                                                const uint32_t* b) {
    asm volatile(
        "mma.sync.aligned.m16n8k16.row.col.f32.bf16.bf16.f32 "
        "{%0,%1,%2,%3}, {%4,%5,%6,%7}, {%8,%9}, {%0,%1,%2,%3};"
        : "+f"(c[0]), "+f"(c[1]), "+f"(c[2]), "+f"(c[3])
        : "r"(a[0]), "r"(a[1]), "r"(a[2]), "r"(a[3]), "r"(b[0]), "r"(b[1]));
}
static __device__ __forceinline__ uint32_t pk_bf2(float a, float b) {
    __nv_bfloat162 t = __floats2bfloat162_rn(a, b);
    return *reinterpret_cast<uint32_t*>(&t);
}

// ---------------------------------------------------------------------------
// bf16x3 HMMA GEMM: C[M,N] = (Ah+Al)[M,K] · (Bh+Bl)[N,K]^T  (both K-major)
// CTA 128x128, 8 warps (2x4), warp tile 64x32, KT=32, 2-stage cp.async.
// smem rows padded to 40 bf16 (80B) -> conflict-free ldmatrix.
// ---------------------------------------------------------------------------
#define KT          32
#define ROWB        80                   /* bytes per smem row (40 bf16) */
#define MAT_BYTES   (128 * ROWB)         /* 10240 */
#define STAGE_BYTES (4 * MAT_BYTES)      /* Ah, Al, Bh, Bl = 40960 */
#define SMEM_GEMM   (2 * STAGE_BYTES)    /* 81920 */

__global__ __launch_bounds__(256, 2)
void gemm_hmma(const __nv_bfloat16* __restrict__ pAh, const __nv_bfloat16* __restrict__ pAl,
               const __nv_bfloat16* __restrict__ pBh, const __nv_bfloat16* __restrict__ pBl,
               float* __restrict__ pC,
               int K, int ldc, long sA, long sB, long sC)
{
    extern __shared__ __align__(128) char smem[];
    const uint32_t sb = smem_u32(smem);

    const int tid  = threadIdx.x;
    const int wid  = tid >> 5;
    const int lane = tid & 31;
    const int wr   = wid & 1;        // warp row (0..1) -> 64 rows each
    const int wc   = wid >> 1;       // warp col (0..3) -> 32 cols each

    const int brow = blockIdx.y << 7;
    const int bcol = blockIdx.x << 7;
    const int bz   = blockIdx.z;

    const __nv_bfloat16* mats[4] = {
        pAh + (size_t)bz * sA + (size_t)brow * K,
        pAl + (size_t)bz * sA + (size_t)brow * K,
        pBh + (size_t)bz * sB + (size_t)bcol * K,
        pBl + (size_t)bz * sB + (size_t)bcol * K
    };

    // loader mapping: this thread services matrix (tid>>6), 8 chunks of 16B
    const int lm   = tid >> 6;          // matrix 0..3
    const int lj0  = tid & 63;          // base chunk within 64-thread group
    const __nv_bfloat16* lsrc = mats[lm];
    const uint32_t ldst = sb + lm * MAT_BYTES;

    auto load_stage = [&](int buf, int t) {
        const int koff = t * KT;
        const uint32_t stage = ldst + buf * STAGE_BYTES;
#pragma unroll
        for (int i = 0; i < 8; ++i) {
            const int j   = i * 64 + lj0;       // 0..511
            const int row = j >> 2;
            const int c16 = j & 3;
            cpa16(stage + row * ROWB + c16 * 16,
                  lsrc + (size_t)row * K + koff + c16 * 8);
        }
        cp_commit();
    };

    float acc[4][4][4];
#pragma unroll
    for (int i = 0; i < 4; ++i)
#pragma unroll
        for (int j = 0; j < 4; ++j)
#pragma unroll
            for (int k = 0; k < 4; ++k) acc[i][j][k] = 0.f;

    const int NT = K / KT;
    load_stage(0, 0);
    load_stage(1, 1);

    // precomputed ldmatrix lane offsets (bytes), pitch ROWB
    const int l7 = lane & 7, l3 = (lane >> 3) & 1, l4 = lane >> 4;
    // A: m = mf*16 + l3*8 + l7 (+wr*64), k = ks*16 + l4*8
    const uint32_t a_off = (uint32_t)((wr * 64 + l3 * 8 + l7) * ROWB + (l4 * 8) * 2);
    // B: n = wc*32 + g*16 + l4*8 + l7, k = ks*16 + l3*8
    const uint32_t b_off = (uint32_t)((wc * 32 + l4 * 8 + l7) * ROWB + (l3 * 8) * 2)
                           + 2u * MAT_BYTES;

    for (int t = 0; t < NT; ++t) {
        if (t + 1 < NT) cp_wait<1>(); else cp_wait<0>();
        __syncthreads();

        const uint32_t stage = sb + (t & 1) * STAGE_BYTES;
#pragma unroll
        for (int ks = 0; ks < 2; ++ks) {
            const uint32_t kb = (uint32_t)(ks * 16 * 2);
            uint32_t bh[8], bl[8];
#pragma unroll
            for (int g = 0; g < 2; ++g) {
                const uint32_t ba = stage + b_off + g * 16 * ROWB + kb;
                ldm4(bh + 4 * g, ba);
                ldm4(bl + 4 * g, ba + MAT_BYTES);
            }
#pragma unroll
            for (int mf = 0; mf < 4; ++mf) {
                const uint32_t aa = stage + a_off + mf * 16 * ROWB + kb;
                uint32_t ah[4], al[4];
                ldm4(ah, aa);
                ldm4(al, aa + MAT_BYTES);
#pragma unroll
                for (int nf = 0; nf < 4; ++nf) {
                    mma16816(acc[mf][nf], ah, bh + 2 * nf);
                    mma16816(acc[mf][nf], ah, bl + 2 * nf);
                    mma16816(acc[mf][nf], al, bh + 2 * nf);
                }
            }
        }
        __syncthreads();
        if (t + 2 < NT) load_stage(t & 1, t + 2);
    }

    // epilogue: direct gmem stores, float2 per fragment half
    const int q  = lane >> 2;       // 0..7
    const int tq = lane & 3;        // 0..3
    float* C = pC + (size_t)bz * sC;
#pragma unroll
    for (int mf = 0; mf < 4; ++mf) {
        const int m0 = brow + wr * 64 + mf * 16 + q;
#pragma unroll
        for (int nf = 0; nf < 4; ++nf) {
            const int n = bcol + wc * 32 + nf * 8 + 2 * tq;
            *(float2*)(C + (size_t)m0 * ldc + n) =
                make_float2(acc[mf][nf][0], acc[mf][nf][1]);
            *(float2*)(C + (size_t)(m0 + 8) * ldc + n) =
                make_float2(acc[mf][nf][2], acc[mf][nf][3]);
        }
    }
}

// ---------------------------------------------------------------------------
// Q -> (Qh, Ql) elementwise hi/lo split, 8 elems/thread
// ---------------------------------------------------------------------------
__global__ __launch_bounds__(256)
void cvt_hilo8(const float* __restrict__ x,
               __nv_bfloat16* __restrict__ h, __nv_bfloat16* __restrict__ l)
{
    const size_t i = ((size_t)blockIdx.x * blockDim.x + threadIdx.x) * 8;
    const float4 a = *(const float4*)(x + i);
    const float4 b = *(const float4*)(x + i + 4);
    const float v[8] = {a.x, a.y, a.z, a.w, b.x, b.y, b.z, b.w};
    float hf[8], lf[8];
#pragma unroll
    for (int j = 0; j < 8; ++j) {
        hf[j] = __bfloat162float(__float2bfloat16(v[j]));
        lf[j] = v[j] - hf[j];
    }
    *(uint4*)(h + i) = make_uint4(pk_bf2(hf[0], hf[1]), pk_bf2(hf[2], hf[3]),
                                  pk_bf2(hf[4], hf[5]), pk_bf2(hf[6], hf[7]));
    *(uint4*)(l + i) = make_uint4(pk_bf2(lf[0], lf[1]), pk_bf2(lf[2], lf[3]),
                                  pk_bf2(lf[4], lf[5]), pk_bf2(lf[6], lf[7]));
}

// ---------------------------------------------------------------------------
// V -> (Vh, Vl) and transposed (VTh, VTl). 32x32 tiles, block (32,8).
// ---------------------------------------------------------------------------
__global__ __launch_bounds__(256)
void cvtV(const float* __restrict__ V,
          __nv_bfloat16* __restrict__ Vh, __nv_bfloat16* __restrict__ Vl,
          __nv_bfloat16* __restrict__ VTh, __nv_bfloat16* __restrict__ VTl)
{
    __shared__ float ts[32][33];
    const int bz = blockIdx.z;
    const float* Vb = V + (size_t)bz * LK * DDIM;
    const int x  = blockIdx.x * 32 + threadIdx.x;   // d
    const int y0 = blockIdx.y * 32 + threadIdx.y;   // k base

#pragma unroll
    for (int j = 0; j < 4; ++j) {
        const int k = y0 + j * 8;
        const float v = Vb[(size_t)k * DDIM + x];
        ts[threadIdx.y + j * 8][threadIdx.x] = v;
        const __nv_bfloat16 hb = __float2bfloat16(v);
        const float hfv = __bfloat162float(hb);
        const size_t o = (size_t)bz * LK * DDIM + (size_t)k * DDIM + x;
        Vh[o] = hb;
        Vl[o] = __float2bfloat16(v - hfv);
    }
    __syncthreads();
#pragma unroll
    for (int j = 0; j < 4; ++j) {
        const int d = blockIdx.x * 32 + threadIdx.y + j * 8;
        const int k = blockIdx.y * 32 + threadIdx.x;
        const float v = ts[threadIdx.x][threadIdx.y + j * 8];
        const __nv_bfloat16 hb = __float2bfloat16(v);
        const float hfv = __bfloat162float(hb);
        const size_t o = (size_t)bz * DDIM * LK + (size_t)d * LK + k;
        VTh[o] = hb;
        VTl[o] = __float2bfloat16(v - hfv);
    }
}

// ---------------------------------------------------------------------------
// Row softmax in place + emit bf16 hi/lo planes of the result.
// ---------------------------------------------------------------------------
__global__ __launch_bounds__(256)
void softmax_rows(float* __restrict__ S,
                  __nv_bfloat16* __restrict__ Ph, __nv_bfloat16* __restrict__ Pl)
{
    __shared__ float redmax[8];
    __shared__ float redsum[8];

    const size_t rowbase = (size_t)blockIdx.x * LK;
    float* p = S + rowbase;
    const int tid  = threadIdx.x;
    const int lane = tid & 31;
    const int warp = tid >> 5;

    const float4 v0 = *(const float4*)(p + tid * 8);
    const float4 v1 = *(const float4*)(p + tid * 8 + 4);

    float m = fmaxf(fmaxf(fmaxf(v0.x, v0.y), fmaxf(v0.z, v0.w)),
                    fmaxf(fmaxf(v1.x, v1.y), fmaxf(v1.z, v1.w)));
#pragma unroll
    for (int o = 16; o > 0; o >>= 1)
        m = fmaxf(m, __shfl_xor_sync(0xffffffffu, m, o));
    if (lane == 0) redmax[warp] = m;
    __syncthreads();
    float bm = redmax[0];
#pragma unroll
    for (int w = 1; w < 8; ++w) bm = fmaxf(bm, redmax[w]);

    float e[8];
    e[0] = __expf(v0.x - bm); e[1] = __expf(v0.y - bm);
    e[2] = __expf(v0.z - bm); e[3] = __expf(v0.w - bm);
    e[4] = __expf(v1.x - bm); e[5] = __expf(v1.y - bm);
    e[6] = __expf(v1.z - bm); e[7] = __expf(v1.w - bm);

    float s = ((e[0] + e[1]) + (e[2] + e[3])) + ((e[4] + e[5]) + (e[6] + e[7]));
#pragma unroll
    for (int o = 16; o > 0; o >>= 1)
        s += __shfl_xor_sync(0xffffffffu, s, o);
    if (lane == 0) redsum[warp] = s;
    __syncthreads();
    float total = redsum[0];
#pragma unroll
    for (int w = 1; w < 8; ++w) total += redsum[w];
    const float inv = 1.0f / total;

    float y[8], hf[8], lf[8];
#pragma unroll
    for (int j = 0; j < 8; ++j) {
        y[j]  = e[j] * inv;
        hf[j] = __bfloat162float(__float2bfloat16(y[j]));
        lf[j] = y[j] - hf[j];
    }
    *(float4*)(p + tid * 8)     = make_float4(y[0], y[1], y[2], y[3]);
    *(float4*)(p + tid * 8 + 4) = make_float4(y[4], y[5], y[6], y[7]);

    const size_t ob = rowbase + (size_t)tid * 8;
    *(uint4*)(Ph + ob) = make_uint4(pk_bf2(hf[0], hf[1]), pk_bf2(hf[2], hf[3]),
                                    pk_bf2(hf[4], hf[5]), pk_bf2(hf[6], hf[7]));
    *(uint4*)(Pl + ob) = make_uint4(pk_bf2(lf[0], lf[1]), pk_bf2(lf[2], lf[3]),
                                    pk_bf2(lf[4], lf[5]), pk_bf2(lf[6], lf[7]));
}

// ---------------------------------------------------------------------------
// kernel_launch
// ---------------------------------------------------------------------------
extern "C" void kernel_launch(void* const* d_in, const int* in_sizes, int n_in,
                              void* d_out, int out_size)
{
    const float* Q = (const float*)d_in[0];
    const float* V = (const float*)d_in[1];
    float* ctx  = (float*)d_out;
    float* attn = ctx + (size_t)BATCH * LQ * DDIM;

    void *qh, *ql, *vh, *vl, *vth, *vtl, *ah, *al;
    cudaGetSymbolAddress(&qh, g_Qh);
    cudaGetSymbolAddress(&ql, g_Ql);
    cudaGetSymbolAddress(&vh, g_Vh);
    cudaGetSymbolAddress(&vl, g_Vl);
    cudaGetSymbolAddress(&vth, g_VTh);
    cudaGetSymbolAddress(&vtl, g_VTl);
    cudaGetSymbolAddress(&ah, g_Ph);
    cudaGetSymbolAddress(&al, g_Pl);

    cudaFuncSetAttribute(gemm_hmma, cudaFuncAttributeMaxDynamicSharedMemorySize,
                         SMEM_GEMM);

    // hi/lo splits
    cvt_hilo8<<<(unsigned)((size_t)BATCH * LQ * DDIM / (256 * 8)), 256>>>(
        Q, (__nv_bfloat16*)qh, (__nv_bfloat16*)ql);
    cvtV<<<dim3(DDIM / 32, LK / 32, BATCH), dim3(32, 8)>>>(
        V, (__nv_bfloat16*)vh, (__nv_bfloat16*)vl,
        (__nv_bfloat16*)vth, (__nv_bfloat16*)vtl);

    // GEMM1: scores = Q · V^T   (M=LQ, N=LK, K=DDIM) -> attn buffer
    gemm_hmma<<<dim3(LK / 128, LQ / 128, BATCH), 256, SMEM_GEMM>>>(
        (const __nv_bfloat16*)qh, (const __nv_bfloat16*)ql,
        (const __nv_bfloat16*)vh, (const __nv_bfloat16*)vl,
        attn, DDIM, LK,
        (long)LQ * DDIM, (long)LK * DDIM, (long)LQ * LK);

    // softmax over key axis (in place) + bf16 hi/lo planes
    softmax_rows<<<BATCH * LQ, 256>>>(attn, (__nv_bfloat16*)ah, (__nv_bfloat16*)al);

    // GEMM2: ctx = attn · V = (Ph+Pl) · (VTh+VTl)^T  (M=LQ, N=DDIM, K=LK)
    gemm_hmma<<<dim3(DDIM / 128, LQ / 128, BATCH), 256, SMEM_GEMM>>>(
        (const __nv_bfloat16*)ah, (const __nv_bfloat16*)al,
        (const __nv_bfloat16*)vth, (const __nv_bfloat16*)vtl,
        ctx, LK, DDIM,
        (long)LQ * LK, (long)DDIM * LK, (long)LQ * DDIM);
}